// round 2
// baseline (speedup 1.0000x reference)
#include <cuda_runtime.h>
#include <cuda_bf16.h>
#include <stdint.h>

#define EPSF 1e-6f

// One warp per sample.
__global__ void runway_loss_kernel(const float* __restrict__ pred,
                                   const unsigned char* __restrict__ mask,
                                   const float* __restrict__ runway,
                                   float* __restrict__ out,
                                   int B, int H) {
    int gwarp = (blockIdx.x * blockDim.x + threadIdx.x) >> 5;
    int lane  = threadIdx.x & 31;

    float contrib = 0.0f;

    if (gwarp < B) {
        const unsigned char* mrow = mask + (size_t)gwarp * H;
        int ones = 0;
        if (((H & 3) == 0) && ((((unsigned long long)mrow) & 3ULL) == 0ULL)) {
            // fast path: coalesced 32-bit reads, popc counts 0x01 bytes
            const unsigned int* mw = (const unsigned int*)mrow;
            int nwords = H >> 2;
            for (int i = lane; i < nwords; i += 32)
                ones += __popc(mw[i]);
        } else {
            for (int i = lane; i < H; i += 32)
                ones += (int)mrow[i];
        }
        // warp reduce
        #pragma unroll
        for (int o = 16; o; o >>= 1)
            ones += __shfl_xor_sync(0xFFFFFFFFu, ones, o);

        if (lane == 0) {
            int L = H - ones;   // valid_lengths

            float rx = runway[(size_t)gwarp * 4 + 2];
            float ry = runway[(size_t)gwarp * 4 + 3];
            float rn = sqrtf(rx * rx + ry * ry) + EPSF;
            rx /= rn; ry /= rn;

            const float* prow = pred + (size_t)gwarp * H * 3;
            float px[4], py[4];
            #pragma unroll
            for (int j = 0; j < 4; j++) {
                int idx = L - 4 + j;
                if (idx < 0) idx = 0;
                if (idx > H - 1) idx = H - 1;
                px[j] = prow[idx * 3 + 0];
                py[j] = prow[idx * 3 + 1];
            }

            float acc = 0.0f;
            #pragma unroll
            for (int j = 0; j < 3; j++) {
                float dx = px[j + 1] - px[j];
                float dy = py[j + 1] - py[j];
                float dn = sqrtf(dx * dx + dy * dy) + EPSF;
                float cs = (dx * rx + dy * ry) / dn;
                float t  = 1.0f - cs;
                acc += t * t;
            }
            contrib = acc * (1.0f / 3.0f);   // mean over N_FINAL-1=3 dirs
        }
    }

    // block reduction of per-warp contributions (lane 0 holds them)
    __shared__ float s[32];
    int wib = threadIdx.x >> 5;
    if (lane == 0) s[wib] = contrib;
    __syncthreads();
    if (threadIdx.x == 0) {
        float sum = 0.0f;
        int nw = blockDim.x >> 5;
        for (int i = 0; i < nw; i++) sum += s[i];
        atomicAdd(out, sum / (float)B);   // SCALE = 1.0
    }
}

__global__ void zero_out_kernel(float* out) {
    out[0] = 0.0f;
}

extern "C" void kernel_launch(void* const* d_in, const int* in_sizes, int n_in,
                              void* d_out, int out_size) {
    const float*         pred   = (const float*)d_in[0];
    // d_in[1] = target_abs (unused by the reference)
    const unsigned char* mask   = (const unsigned char*)d_in[2];
    const float*         runway = (const float*)d_in[3];
    float*               out    = (float*)d_out;

    int B = in_sizes[3] / 4;          // runway is (B, 4)
    int H = in_sizes[2] / B;          // mask is (B, H)

    zero_out_kernel<<<1, 1>>>(out);

    const int THREADS = 256;                  // 8 warps/block -> 8 samples/block
    int warps_needed = B;
    int blocks = (warps_needed * 32 + THREADS - 1) / THREADS;
    runway_loss_kernel<<<blocks, THREADS>>>(pred, mask, runway, out, B, H);
}

// round 3
// speedup vs baseline: 2.0930x; 2.0930x over previous
#include <cuda_runtime.h>
#include <cuda_bf16.h>
#include <stdint.h>

#define EPSF 1e-6f

__device__ double g_acc;

__global__ void zero_acc_kernel() {
    g_acc = 0.0;
}

__global__ void finalize_kernel(float* out, int B) {
    out[0] = (float)(g_acc / (double)B);
}

// Thread-per-sample main kernel, specialized on W = H/4 (mask words per row).
template<int W>
__global__ void __launch_bounds__(256) runway_loss_kernel(
        const float* __restrict__ pred,
        const unsigned char* __restrict__ mask,
        const float* __restrict__ runway,
        int B) {
    constexpr int TPB = 256;
    constexpr int H = 4 * W;
    __shared__ uint32_t sm[W * TPB];

    int s0 = blockIdx.x * TPB;
    int nsmp = B - s0; if (nsmp > TPB) nsmp = TPB;
    int nwords = nsmp * W;

    // Coalesced staging of this block's mask slab into smem.
    const uint32_t* mw = (const uint32_t*)mask + (size_t)s0 * W;
    if ((nwords & 3) == 0 && ((((unsigned long long)mw) & 15ULL) == 0ULL)) {
        const uint4* mv = (const uint4*)mw;
        uint4* sv = (uint4*)sm;
        int nvec = nwords >> 2;
        for (int i = threadIdx.x; i < nvec; i += TPB) sv[i] = mv[i];
    } else {
        for (int i = threadIdx.x; i < nwords; i += TPB) sm[i] = mw[i];
    }
    __syncthreads();

    float contrib = 0.0f;
    int s = s0 + threadIdx.x;
    if (threadIdx.x < nsmp) {
        // popc my row (bool bytes are 0x00/0x01)
        const uint32_t* row = sm + threadIdx.x * W;
        int ones = 0;
        #pragma unroll
        for (int j = 0; j < W; j++) ones += __popc(row[j]);
        int L = H - ones;                      // valid length

        // runway direction (last two floats of the 4-float row)
        float rx = runway[(size_t)s * 4 + 2];
        float ry = runway[(size_t)s * 4 + 3];
        float rn = sqrtf(rx * rx + ry * ry) + EPSF;
        rx /= rn; ry /= rn;

        // gather last 4 (x, y) predicted positions
        const float* prow = pred + (size_t)s * H * 3;
        float px[4], py[4];
        #pragma unroll
        for (int j = 0; j < 4; j++) {
            int idx = L - 4 + j;
            if (idx < 0) idx = 0;
            if (idx > H - 1) idx = H - 1;
            px[j] = prow[idx * 3 + 0];
            py[j] = prow[idx * 3 + 1];
        }

        float acc = 0.0f;
        #pragma unroll
        for (int j = 0; j < 3; j++) {
            float dx = px[j + 1] - px[j];
            float dy = py[j + 1] - py[j];
            float dn = sqrtf(dx * dx + dy * dy) + EPSF;
            float cs = (dx * rx + dy * ry) / dn;
            float t  = 1.0f - cs;
            acc += t * t;
        }
        contrib = acc * (1.0f / 3.0f);
    }

    // block reduction (fp32 tree) then one double atomic per block
    __shared__ float red[TPB];
    red[threadIdx.x] = contrib;
    __syncthreads();
    #pragma unroll
    for (int o = TPB / 2; o >= 32; o >>= 1) {
        if (threadIdx.x < o) red[threadIdx.x] += red[threadIdx.x + o];
        __syncthreads();
    }
    if (threadIdx.x < 32) {
        float v = red[threadIdx.x];
        #pragma unroll
        for (int o = 16; o; o >>= 1)
            v += __shfl_xor_sync(0xFFFFFFFFu, v, o);
        if (threadIdx.x == 0)
            atomicAdd(&g_acc, (double)v);
    }
}

// Generic fallback (thread-per-sample, byte loads) for unexpected H.
__global__ void runway_loss_generic(const float* __restrict__ pred,
                                    const unsigned char* __restrict__ mask,
                                    const float* __restrict__ runway,
                                    int B, int H) {
    int s = blockIdx.x * blockDim.x + threadIdx.x;
    float contrib = 0.0f;
    if (s < B) {
        const unsigned char* mrow = mask + (size_t)s * H;
        int ones = 0;
        for (int i = 0; i < H; i++) ones += (int)mrow[i];
        int L = H - ones;
        float rx = runway[(size_t)s * 4 + 2];
        float ry = runway[(size_t)s * 4 + 3];
        float rn = sqrtf(rx * rx + ry * ry) + EPSF;
        rx /= rn; ry /= rn;
        const float* prow = pred + (size_t)s * H * 3;
        float px[4], py[4];
        for (int j = 0; j < 4; j++) {
            int idx = L - 4 + j;
            if (idx < 0) idx = 0;
            if (idx > H - 1) idx = H - 1;
            px[j] = prow[idx * 3 + 0];
            py[j] = prow[idx * 3 + 1];
        }
        float acc = 0.0f;
        for (int j = 0; j < 3; j++) {
            float dx = px[j + 1] - px[j];
            float dy = py[j + 1] - py[j];
            float dn = sqrtf(dx * dx + dy * dy) + EPSF;
            float cs = (dx * rx + dy * ry) / dn;
            float t  = 1.0f - cs;
            acc += t * t;
        }
        contrib = acc * (1.0f / 3.0f);
    }
    __shared__ float red[256];
    red[threadIdx.x] = contrib;
    __syncthreads();
    for (int o = blockDim.x / 2; o >= 32; o >>= 1) {
        if (threadIdx.x < o) red[threadIdx.x] += red[threadIdx.x + o];
        __syncthreads();
    }
    if (threadIdx.x < 32) {
        float v = red[threadIdx.x];
        for (int o = 16; o; o >>= 1)
            v += __shfl_xor_sync(0xFFFFFFFFu, v, o);
        if (threadIdx.x == 0)
            atomicAdd(&g_acc, (double)v);
    }
}

extern "C" void kernel_launch(void* const* d_in, const int* in_sizes, int n_in,
                              void* d_out, int out_size) {
    const float*         pred   = (const float*)d_in[0];
    // d_in[1] = target_abs (unused by the reference)
    const unsigned char* mask   = (const unsigned char*)d_in[2];
    const float*         runway = (const float*)d_in[3];
    float*               out    = (float*)d_out;

    int B = in_sizes[3] / 4;          // runway is (B, 4)
    int H = in_sizes[2] / B;          // mask is (B, H)

    zero_acc_kernel<<<1, 1>>>();

    const int TPB = 256;
    int blocks = (B + TPB - 1) / TPB;
    if (H == 120) {
        runway_loss_kernel<30><<<blocks, TPB>>>(pred, mask, runway, B);
    } else {
        runway_loss_generic<<<blocks, TPB>>>(pred, mask, runway, B, H);
    }

    finalize_kernel<<<1, 1>>>(out, B);
}